// round 2
// baseline (speedup 1.0000x reference)
#include <cuda_runtime.h>
#include <cstddef>

#define BB  64
#define NNODE 1000
#define EE  64
#define OO  16
#define HH  128
#define FUT 12
#define G4  512   // 4*H

// ---------------- device scratch (static, no allocations) ----------------
__device__ float g_nm[(size_t)BB * NNODE * OO];            // 4 MB  : node_mean
__device__ float g_genc[(size_t)BB * NNODE * G4];          // 131 MB: enc@W_e^T + b_ih0 + b_hh0

// ---------------- kernel 1: node_mean = mean(mean, axis=FUT) -------------
__global__ void nm_kernel(const float* __restrict__ mean) {
    int idx = blockIdx.x * blockDim.x + threadIdx.x;      // over B*N*O
    if (idx >= BB * NNODE * OO) return;
    int o = idx & (OO - 1);
    int n = (idx >> 4) % NNODE;
    int b = idx / (NNODE * OO);
    float s = 0.f;
#pragma unroll
    for (int f = 0; f < FUT; f++)
        s += mean[(((size_t)b * FUT + f) * NNODE + n) * OO + o];
    g_nm[idx] = s * (1.0f / FUT);
}

// ---------------- kernel 2: G_enc precompute ------------------------------
// G_enc[r][g] = sum_e W_ih_l0[g][e] * enc[r][e] + b_ih_l0[g] + b_hh_l0[g]
__global__ __launch_bounds__(512) void genc_kernel(
    const float* __restrict__ enc,
    const float* __restrict__ Wih0,
    const float* __restrict__ bih0,
    const float* __restrict__ bhh0)
{
    int g = threadIdx.x;                                   // gate 0..511
    float w[64];
#pragma unroll
    for (int e = 0; e < 64; e++) w[e] = Wih0[g * 80 + e];
    float bias = bih0[g] + bhh0[g];

    __shared__ __align__(16) float4 xs[16];                // one enc row (64 f)
    int total = BB * NNODE;
    int per = (total + gridDim.x - 1) / gridDim.x;
    int r0 = blockIdx.x * per;
    int r1 = min(r0 + per, total);
    for (int r = r0; r < r1; r++) {
        __syncthreads();
        if (g < 16) xs[g] = ((const float4*)(enc + (size_t)r * 64))[g];
        __syncthreads();
        float acc = bias;
#pragma unroll
        for (int e4 = 0; e4 < 16; e4++) {
            float4 x = xs[e4];
            acc += w[e4*4+0]*x.x + w[e4*4+1]*x.y + w[e4*4+2]*x.z + w[e4*4+3]*x.w;
        }
        g_genc[(size_t)r * G4 + g] = acc;
    }
}

// ---------------- kernel 3: sequential recurrence --------------------------
__device__ __forceinline__ float sigm(float x) {
    return 1.0f / (1.0f + expf(-x));
}

__global__ __launch_bounds__(256, 1) void rec_kernel(
    const float* __restrict__ s0,    // (1,16)
    const float* __restrict__ h0,    // (2,16)
    const float* __restrict__ c0,    // (2,128)
    const float* __restrict__ Wih0,  // (512,80)
    const float* __restrict__ Whh0,  // (512,16)
    const float* __restrict__ Whr0,  // (16,128)
    const float* __restrict__ Wih1,  // (512,16)
    const float* __restrict__ Whh1,  // (512,16)
    const float* __restrict__ bih1,  // (512)
    const float* __restrict__ bhh1,  // (512)
    const float* __restrict__ Whr1,  // (16,128)
    float* __restrict__ out)         // (B,FUT,N,O)
{
    const int b   = blockIdx.x;      // one batch element per CTA
    const int tid = threadIdx.x;
    const int k   = tid & 127;       // hidden unit id within layer
    const bool isL0 = tid < 128;     // warps 0-3: layer0, warps 4-7: layer1

    __shared__ __align__(16) float s_last[16];
    __shared__ __align__(16) float s_h1[16];
    __shared__ __align__(16) float s_h2[16];
    __shared__ __align__(16) float s_nm[16];
    __shared__ __align__(16) float s_hf[128];

    // register-resident weights: wa,wb are the two K=16 dot operands for the
    // 4 gate rows this thread owns (layer 0 or layer 1 depending on tid).
    float wa[4][16], wb[4][16], bias[4];
    float wpr[16];                   // projection weights (16-elem segment)
    float c_reg;                     // c1[k] (L0 threads) or c2[k] (L1 threads)

    {
        int o = k >> 3, gl = k & 7;
        if (isL0) {
#pragma unroll
            for (int q = 0; q < 4; q++) {
                int g = q * 128 + k;
#pragma unroll
                for (int j = 0; j < 16; j++) {
                    wa[q][j] = Wih0[g * 80 + 64 + j];   // multiplies loop=last+nm
                    wb[q][j] = Whh0[g * 16 + j];        // multiplies h1_prev
                }
                bias[q] = 0.f;                          // bias folded into G_enc
            }
            c_reg = c0[k];
#pragma unroll
            for (int j = 0; j < 16; j++) wpr[j] = Whr0[o * 128 + gl * 16 + j];
        } else {
#pragma unroll
            for (int q = 0; q < 4; q++) {
                int g = q * 128 + k;
#pragma unroll
                for (int j = 0; j < 16; j++) {
                    wa[q][j] = Wih1[g * 16 + j];        // multiplies h1_new
                    wb[q][j] = Whh1[g * 16 + j];        // multiplies h2_prev
                }
                bias[q] = bih1[g] + bhh1[g];
            }
            c_reg = c0[128 + k];
#pragma unroll
            for (int j = 0; j < 16; j++) wpr[j] = Whr1[o * 128 + gl * 16 + j];
        }
    }

    if (tid < 16) {
        s_last[tid] = s0[tid];         // last0 = s[0]
        s_h1[tid]   = h0[tid];         // h1_0  = h_0[0]
        s_h2[tid]   = h0[16 + tid];    // h2_0  = h_0[1]
    }

    // node-ahead prefetch state
    float genc_c[4], genc_n[4], gnm[4];
    float nm_pref = 0.f;
    if (isL0) {
        size_t base = ((size_t)b * NNODE + 0) * G4 + k;
#pragma unroll
        for (int q = 0; q < 4; q++) genc_n[q] = g_genc[base + q * 128];
    } else if (k < 16) {
        nm_pref = g_nm[(size_t)b * NNODE * OO + k];
    }

    int n = 0, f = 0;
    for (int t = 0; t < NNODE * FUT; t++) {
        if (f == 0) {
            // ---- node boundary: publish nm, fold gnm, prefetch node n+1 ----
            if (!isL0 && k < 16) s_nm[k] = nm_pref;
            __syncthreads();
            if (isL0) {
#pragma unroll
                for (int q = 0; q < 4; q++) genc_c[q] = genc_n[q];
#pragma unroll
                for (int q = 0; q < 4; q++) {
                    float a = 0.f;
#pragma unroll
                    for (int j = 0; j < 16; j++) a += wa[q][j] * s_nm[j];
                    gnm[q] = a;       // W_loop . nm  (constant for this node)
                }
                int nn = (n + 1 < NNODE) ? n + 1 : n;
                size_t base = ((size_t)b * NNODE + nn) * G4 + k;
#pragma unroll
                for (int q = 0; q < 4; q++) genc_n[q] = g_genc[base + q * 128];
            } else if (k < 16) {
                int nn = (n + 1 < NNODE) ? n + 1 : n;
                nm_pref = g_nm[((size_t)b * NNODE + nn) * OO + k];
            }
        }

        float acc0, acc1, acc2, acc3;
        if (isL0) {
            // ---- P1: layer0 gates + activation + c1 update (exchange-free) ----
            acc0 = genc_c[0] + gnm[0];
            acc1 = genc_c[1] + gnm[1];
            acc2 = genc_c[2] + gnm[2];
            acc3 = genc_c[3] + gnm[3];
            const float4* l4 = (const float4*)s_last;
            const float4* h4 = (const float4*)s_h1;
#pragma unroll
            for (int j4 = 0; j4 < 4; j4++) {
                float4 xl = l4[j4];
                float4 xh = h4[j4];
                float xlv[4] = {xl.x, xl.y, xl.z, xl.w};
                float xhv[4] = {xh.x, xh.y, xh.z, xh.w};
#pragma unroll
                for (int jj = 0; jj < 4; jj++) {
                    int j = j4 * 4 + jj;
                    acc0 += wa[0][j] * xlv[jj] + wb[0][j] * xhv[jj];
                    acc1 += wa[1][j] * xlv[jj] + wb[1][j] * xhv[jj];
                    acc2 += wa[2][j] * xlv[jj] + wb[2][j] * xhv[jj];
                    acc3 += wa[3][j] * xlv[jj] + wb[3][j] * xhv[jj];
                }
            }
            float ig = sigm(acc0), fg = sigm(acc1);
            float gg = tanhf(acc2), og = sigm(acc3);
            c_reg = fg * c_reg + ig * gg;
            s_hf[k] = og * tanhf(c_reg);
        } else {
            // ---- layer1 partial: b1 + W_hh1 . h2_prev (available now) ----
            acc0 = bias[0]; acc1 = bias[1]; acc2 = bias[2]; acc3 = bias[3];
            const float4* h24 = (const float4*)s_h2;
#pragma unroll
            for (int j4 = 0; j4 < 4; j4++) {
                float4 x = h24[j4];
                float xv[4] = {x.x, x.y, x.z, x.w};
#pragma unroll
                for (int jj = 0; jj < 4; jj++) {
                    int j = j4 * 4 + jj;
                    acc0 += wb[0][j] * xv[jj];
                    acc1 += wb[1][j] * xv[jj];
                    acc2 += wb[2][j] * xv[jj];
                    acc3 += wb[3][j] * xv[jj];
                }
            }
        }
        __syncthreads();   // bar1: hf(layer0) visible

        if (isL0) {
            // ---- P2: projection h1 = W_hr0 @ hf (8 lanes per output) ----
            int gl = k & 7;
            const float4* hf4 = (const float4*)(s_hf + gl * 16);
            float p = 0.f;
#pragma unroll
            for (int j4 = 0; j4 < 4; j4++) {
                float4 x = hf4[j4];
                p += wpr[j4*4+0]*x.x + wpr[j4*4+1]*x.y + wpr[j4*4+2]*x.z + wpr[j4*4+3]*x.w;
            }
            p += __shfl_xor_sync(0xffffffffu, p, 4);
            p += __shfl_xor_sync(0xffffffffu, p, 2);
            p += __shfl_xor_sync(0xffffffffu, p, 1);
            if (gl == 0) s_h1[k >> 3] = p;
        }
        __syncthreads();   // bar2: h1 visible, hf free

        if (!isL0) {
            // ---- P3: layer1 gates finish + activation + c2 update ----
            const float4* h14 = (const float4*)s_h1;
#pragma unroll
            for (int j4 = 0; j4 < 4; j4++) {
                float4 x = h14[j4];
                float xv[4] = {x.x, x.y, x.z, x.w};
#pragma unroll
                for (int jj = 0; jj < 4; jj++) {
                    int j = j4 * 4 + jj;
                    acc0 += wa[0][j] * xv[jj];
                    acc1 += wa[1][j] * xv[jj];
                    acc2 += wa[2][j] * xv[jj];
                    acc3 += wa[3][j] * xv[jj];
                }
            }
            float ig = sigm(acc0), fg = sigm(acc1);
            float gg = tanhf(acc2), og = sigm(acc3);
            c_reg = fg * c_reg + ig * gg;
            s_hf[k] = og * tanhf(c_reg);
        }
        __syncthreads();   // bar3: hf(layer1) visible

        if (!isL0) {
            // ---- P4: projection h2 = W_hr1 @ hf2, publish state + output ----
            int gl = k & 7;
            const float4* hf4 = (const float4*)(s_hf + gl * 16);
            float p = 0.f;
#pragma unroll
            for (int j4 = 0; j4 < 4; j4++) {
                float4 x = hf4[j4];
                p += wpr[j4*4+0]*x.x + wpr[j4*4+1]*x.y + wpr[j4*4+2]*x.z + wpr[j4*4+3]*x.w;
            }
            p += __shfl_xor_sync(0xffffffffu, p, 4);
            p += __shfl_xor_sync(0xffffffffu, p, 2);
            p += __shfl_xor_sync(0xffffffffu, p, 1);
            if (gl == 0) {
                int o = k >> 3;
                s_h2[o]   = p;
                s_last[o] = p;    // carry: last = h2
                out[(((size_t)b * FUT + f) * NNODE + n) * OO + o] = p + s_nm[o];
            }
        }
        __syncthreads();   // bar4: state visible for next step

        if (++f == FUT) { f = 0; ++n; }
    }
}

// ---------------- launch ----------------------------------------------------
extern "C" void kernel_launch(void* const* d_in, const int* in_sizes, int n_in,
                              void* d_out, int out_size)
{
    const float* enc  = (const float*)d_in[0];   // (64,1,1000,64)
    const float* mean = (const float*)d_in[1];   // (64,12,1000,16)
    const float* s    = (const float*)d_in[2];   // (1,16)
    const float* h0   = (const float*)d_in[3];   // (2,16)
    const float* c0   = (const float*)d_in[4];   // (2,128)
    const float* Wih0 = (const float*)d_in[5];   // (512,80)
    const float* Whh0 = (const float*)d_in[6];   // (512,16)
    const float* bih0 = (const float*)d_in[7];   // (512)
    const float* bhh0 = (const float*)d_in[8];   // (512)
    const float* Whr0 = (const float*)d_in[9];   // (16,128)
    const float* Wih1 = (const float*)d_in[10];  // (512,16)
    const float* Whh1 = (const float*)d_in[11];  // (512,16)
    const float* bih1 = (const float*)d_in[12];  // (512)
    const float* bhh1 = (const float*)d_in[13];  // (512)
    const float* Whr1 = (const float*)d_in[14];  // (16,128)
    float* out = (float*)d_out;                  // (64,12,1000,16) fp32

    nm_kernel<<<(BB * NNODE * OO + 255) / 256, 256>>>(mean);
    genc_kernel<<<148, 512>>>(enc, Wih0, bih0, bhh0);
    rec_kernel<<<BB, 256>>>(s, h0, c0, Wih0, Whh0, Whr0,
                            Wih1, Whh1, bih1, bhh1, Whr1, out);
}